// round 9
// baseline (speedup 1.0000x reference)
#include <cuda_runtime.h>

// ---------------- problem constants (from reference) ----------------
#define NMAX   100000
#define EMAX   1700032
#define NEG_SLOPE 0.2f

__device__ __forceinline__ void fma4(float4& acc, float s, const float4& wv) {
    acc.x = fmaf(s, wv.x, acc.x); acc.y = fmaf(s, wv.y, acc.y);
    acc.z = fmaf(s, wv.z, acc.z); acc.w = fmaf(s, wv.w, acc.w);
}
__device__ __forceinline__ float lrelu(float v) {
    return (v > 0.0f) ? v : NEG_SLOPE * v;
}

// ---------------- scratch (device globals) --------------------------
__device__ __align__(16) float g_hlin1[NMAX * 32];   // x@W1 (pre-bias)
__device__ float g_as1[NMAX];
__device__ float g_ad1[NMAX];

__device__ __align__(16) float g_h23[NMAX * 32];     // interleaved mu|ls
__device__ __align__(8)  float g_src23[NMAX * 2];
__device__ __align__(8)  float g_dst23[NMAX * 2];

__device__ __align__(8)  int2  g_edges[EMAX];
__device__ int   g_deg[NMAX];
__device__ int   g_off[NMAX + 1];
__device__ int   g_cur[NMAX];
__device__ int   g_bsum[128];
__device__ int   g_csr[EMAX];        // src ids grouped by dst
__device__ int   g_is64;

// ---------------- CSR build -----------------------------------------

__global__ void k_detect(const unsigned int* __restrict__ p, int emain) {
    __shared__ int bad;
    if (threadIdx.x == 0) bad = 0;
    __syncthreads();
    int cnt = 2 * emain; if (cnt > 8192) cnt = 8192;
    for (int i = 1 + 2 * threadIdx.x; i < cnt; i += 2 * blockDim.x)
        if (p[i] != 0u) bad = 1;
    __syncthreads();
    if (threadIdx.x == 0) g_is64 = bad ? 0 : 1;
}

__global__ __launch_bounds__(256) void k_zerodeg(int n) {
    int i = blockIdx.x * blockDim.x + threadIdx.x;
    int stride = gridDim.x * blockDim.x;
    for (int j = i; j < n; j += stride) g_deg[j] = 0;
}

// decode edges (+ self loops) AND accumulate degree histogram
__global__ __launch_bounds__(256) void k_prep(const void* __restrict__ ei,
                                              int emain, int n) {
    int etot = emain + n;
    int stride = gridDim.x * blockDim.x;
    int tid0 = blockIdx.x * blockDim.x + threadIdx.x;
    int is64 = g_is64;
    for (int e = tid0; e < etot; e += stride) {
        int s, d;
        if (e >= emain) { s = d = e - emain; }
        else if (is64) {
            const long long* p = (const long long*)ei;
            s = (int)p[e]; d = (int)p[emain + e];
        } else {
            const int* p = (const int*)ei;
            s = p[e]; d = p[emain + e];
        }
        g_edges[e] = make_int2(s, d);
        atomicAdd(&g_deg[d], 1);
    }
}

// block-level exclusive scan: 1024 elems/block, 4/thread
__global__ __launch_bounds__(256) void k_scanA(int n) {
    __shared__ int ts[256];
    int b = blockIdx.x, tid = threadIdx.x;
    int base = b * 1024 + tid * 4;
    int v0 = (base + 0 < n) ? g_deg[base + 0] : 0;
    int v1 = (base + 1 < n) ? g_deg[base + 1] : 0;
    int v2 = (base + 2 < n) ? g_deg[base + 2] : 0;
    int v3 = (base + 3 < n) ? g_deg[base + 3] : 0;
    int tsum = v0 + v1 + v2 + v3;
    ts[tid] = tsum;
    __syncthreads();
    #pragma unroll
    for (int d = 1; d < 256; d <<= 1) {
        int t = (tid >= d) ? ts[tid - d] : 0;
        __syncthreads();
        ts[tid] += t;
        __syncthreads();
    }
    int excl = (tid > 0) ? ts[tid - 1] : 0;
    int run = excl;
    if (base + 0 < n) { g_off[base + 0] = run; } run += v0;
    if (base + 1 < n) { g_off[base + 1] = run; } run += v1;
    if (base + 2 < n) { g_off[base + 2] = run; } run += v2;
    if (base + 3 < n) { g_off[base + 3] = run; } run += v3;
    if (tid == 255) g_bsum[b] = ts[255];
}

__global__ void k_scanB(int nblk) {
    __shared__ int s[128];
    int tid = threadIdx.x;
    s[tid] = (tid < nblk) ? g_bsum[tid] : 0;
    __syncthreads();
    #pragma unroll
    for (int d = 1; d < 128; d <<= 1) {
        int t = (tid >= d) ? s[tid - d] : 0;
        __syncthreads();
        s[tid] += t;
        __syncthreads();
    }
    if (tid < nblk) g_bsum[tid] = (tid > 0) ? s[tid - 1] : 0;
}

__global__ __launch_bounds__(256) void k_scanC(int n, int etot) {
    int b = blockIdx.x, tid = threadIdx.x;
    int add = g_bsum[b];
    int base = b * 1024 + tid * 4;
    #pragma unroll
    for (int j = 0; j < 4; j++) {
        int i = base + j;
        if (i < n) {
            int v = g_off[i] + add;
            g_off[i] = v;
            g_cur[i] = v;
        }
    }
    if (b == 0 && tid == 0) g_off[n] = etot;
}

__global__ __launch_bounds__(256) void k_scatter(int etot) {
    int stride = gridDim.x * blockDim.x;
    for (int e = blockIdx.x * blockDim.x + threadIdx.x; e < etot; e += stride) {
        int2 ed = g_edges[e];
        int pos = atomicAdd(&g_cur[ed.y], 1);
        g_csr[pos] = ed.x;
    }
}

// ---------------- compute kernels -----------------------------------

// hlin1 = x @ W1 ; attention dots. 2 nodes/thread, x read direct from
// global (8-lane broadcast per LDG.128); only W staged in smem.
__global__ __launch_bounds__(256) void k_gemm1(
    const float* __restrict__ x, const float* __restrict__ W1,
    const float* __restrict__ a1s, const float* __restrict__ a1d, int n)
{
    __shared__ float4 Ws4[128 * 8];    // [k][q] = W1[k][4q..4q+3]
    __shared__ float4 as4[8], ad4[8];
    int tid = threadIdx.x;
    const float4* W4 = (const float4*)W1;
    for (int i = tid; i < 1024; i += 256) Ws4[i] = W4[i];
    if (tid < 8)        as4[tid]     = ((const float4*)a1s)[tid];
    else if (tid < 16)  ad4[tid - 8] = ((const float4*)a1d)[tid - 8];
    __syncthreads();

    int warp = tid >> 5, lane = tid & 31;
    int pair = lane >> 3, q = lane & 7;
    int nodeL0 = warp * 8 + pair * 2;
    int node0 = blockIdx.x * 64 + nodeL0;
    int node1 = node0 + 1;
    if (node0 >= n) return;
    bool has1 = (node1 < n);

    const float4* xr0 = (const float4*)x + (size_t)node0 * 32;
    const float4* xr1 = xr0 + (has1 ? 32 : 0);
    float4 acc0 = make_float4(0.f, 0.f, 0.f, 0.f);
    float4 acc1 = make_float4(0.f, 0.f, 0.f, 0.f);
    #pragma unroll 4
    for (int k4 = 0; k4 < 32; k4++) {
        float4 xv0 = xr0[k4];
        float4 xv1 = xr1[k4];
        float4 w0 = Ws4[(k4 * 4 + 0) * 8 + q];
        float4 w1 = Ws4[(k4 * 4 + 1) * 8 + q];
        float4 w2 = Ws4[(k4 * 4 + 2) * 8 + q];
        float4 w3 = Ws4[(k4 * 4 + 3) * 8 + q];
        fma4(acc0, xv0.x, w0); fma4(acc1, xv1.x, w0);
        fma4(acc0, xv0.y, w1); fma4(acc1, xv1.y, w1);
        fma4(acc0, xv0.z, w2); fma4(acc1, xv1.z, w2);
        fma4(acc0, xv0.w, w3); fma4(acc1, xv1.w, w3);
    }

    float4 av = as4[q], dv = ad4[q];
    float ts0 = acc0.x * av.x + acc0.y * av.y + acc0.z * av.z + acc0.w * av.w;
    float td0 = acc0.x * dv.x + acc0.y * dv.y + acc0.z * dv.z + acc0.w * dv.w;
    float ts1 = acc1.x * av.x + acc1.y * av.y + acc1.z * av.z + acc1.w * av.w;
    float td1 = acc1.x * dv.x + acc1.y * dv.y + acc1.z * dv.z + acc1.w * dv.w;
    #pragma unroll
    for (int off = 4; off >= 1; off >>= 1) {
        ts0 += __shfl_xor_sync(0xffffffffu, ts0, off);
        td0 += __shfl_xor_sync(0xffffffffu, td0, off);
        ts1 += __shfl_xor_sync(0xffffffffu, ts1, off);
        td1 += __shfl_xor_sync(0xffffffffu, td1, off);
    }
    ((float4*)(g_hlin1 + (size_t)node0 * 32))[q] = acc0;
    if (q == 0) { g_as1[node0] = ts0; g_ad1[node0] = td0; }
    if (has1) {
        ((float4*)(g_hlin1 + (size_t)node1 * 32))[q] = acc1;
        if (q == 0) { g_as1[node1] = ts1; g_ad1[node1] = td1; }
    }
}

// Fused layer-1 gather + layer-2 linear:
// h1 = relu(gather-softmax + b1) computed in-register (never stored),
// h23 = h1 @ [Wmu|Wls] via 8-lane shuffle matmul, plus attention dots.
__global__ __launch_bounds__(256) void k_gather1(
    const float* __restrict__ b1,
    const float* __restrict__ Wmu, const float* __restrict__ amus,
    const float* __restrict__ amud,
    const float* __restrict__ Wls, const float* __restrict__ alss,
    const float* __restrict__ alsd, int n)
{
    __shared__ float Wcat[32 * 32];      // [k][c]: c<16 mu, c>=16 ls
    __shared__ float4 b1s4[8];
    __shared__ float4 srcv4[8], dstv4[8];
    int tid = threadIdx.x;
    for (int i = tid; i < 1024; i += 256) {
        int k = i >> 5, c = i & 31;
        Wcat[i] = (c < 16) ? Wmu[k * 16 + c] : Wls[k * 16 + (c - 16)];
    }
    if (tid < 8) b1s4[tid] = ((const float4*)b1)[tid];
    if (tid < 32) {
        float sv = (tid < 16) ? amus[tid] : alss[tid - 16];
        float dv = (tid < 16) ? amud[tid] : alsd[tid - 16];
        ((float*)srcv4)[tid] = sv;
        ((float*)dstv4)[tid] = dv;
    }
    __syncthreads();

    int t = blockIdx.x * blockDim.x + tid;
    int node = t >> 3;
    bool act = (node < n);
    if (!act) node = n - 1;
    int lane = tid & 31;
    int q = lane & 7;
    int gbase = lane & 24;               // 8-lane group base within warp

    float ad = g_ad1[node];
    int off0 = g_off[node], off1 = g_off[node + 1];
    float4 acc = make_float4(0.f, 0.f, 0.f, 0.f);
    float s = 0.0f;
    #pragma unroll 4
    for (int i = off0; i < off1; i++) {
        int src = g_csr[i];
        float ex = __expf(lrelu(g_as1[src] + ad));
        float4 h = ((const float4*)(g_hlin1 + (size_t)src * 32))[q];
        fma4(acc, ex, h);
        s += ex;
    }
    float inv = __frcp_rn(s);
    float4 bb = b1s4[q];
    float4 h1;
    h1.x = fmaxf(fmaf(acc.x, inv, bb.x), 0.f);
    h1.y = fmaxf(fmaf(acc.y, inv, bb.y), 0.f);
    h1.z = fmaxf(fmaf(acc.z, inv, bb.z), 0.f);
    h1.w = fmaxf(fmaf(acc.w, inv, bb.w), 0.f);

    // 32x32 matmul: shuffle-broadcast h1 across the 8-lane group.
    const float4* Wc4 = (const float4*)Wcat;
    float4 o = make_float4(0.f, 0.f, 0.f, 0.f);
    #pragma unroll
    for (int r = 0; r < 8; r++) {
        float hx = __shfl_sync(0xffffffffu, h1.x, gbase + r);
        float hy = __shfl_sync(0xffffffffu, h1.y, gbase + r);
        float hz = __shfl_sync(0xffffffffu, h1.z, gbase + r);
        float hw = __shfl_sync(0xffffffffu, h1.w, gbase + r);
        fma4(o, hx, Wc4[(4 * r + 0) * 8 + q]);
        fma4(o, hy, Wc4[(4 * r + 1) * 8 + q]);
        fma4(o, hz, Wc4[(4 * r + 2) * 8 + q]);
        fma4(o, hw, Wc4[(4 * r + 3) * 8 + q]);
    }

    float4 av = srcv4[q], dv = dstv4[q];
    float ts = o.x * av.x + o.y * av.y + o.z * av.z + o.w * av.w;
    float td = o.x * dv.x + o.y * dv.y + o.z * dv.z + o.w * dv.w;
    #pragma unroll
    for (int off = 2; off >= 1; off >>= 1) {   // reduce within 4-lane half
        ts += __shfl_xor_sync(0xffffffffu, ts, off);
        td += __shfl_xor_sync(0xffffffffu, td, off);
    }
    if (act) {
        ((float4*)(g_h23 + (size_t)node * 32))[q] = o;
        if (q == 0) { g_src23[2 * node + 0] = ts; g_dst23[2 * node + 0] = td; }
        if (q == 4) { g_src23[2 * node + 1] = ts; g_dst23[2 * node + 1] = td; }
    }
}

// Layer-2 gather (mu+ls fused): 8 lanes per dst node; writes final output.
__global__ __launch_bounds__(256) void k_gather23(
    const float* __restrict__ bmu, const float* __restrict__ bls,
    float* __restrict__ out, int n)
{
    int t = blockIdx.x * blockDim.x + threadIdx.x;
    int node = t >> 3;
    if (node >= n) return;
    int q = t & 7;
    float2 dv = *(const float2*)(g_dst23 + 2 * node);
    int off0 = g_off[node], off1 = g_off[node + 1];
    float4 acc = make_float4(0.f, 0.f, 0.f, 0.f);
    float smu = 0.0f, sls = 0.0f;
    bool is_mu = (q < 4);
    #pragma unroll 4
    for (int i = off0; i < off1; i++) {
        int src = g_csr[i];
        float2 sv = *(const float2*)(g_src23 + 2 * src);
        float exmu = __expf(lrelu(sv.x + dv.x));
        float exls = __expf(lrelu(sv.y + dv.y));
        smu += exmu; sls += exls;
        float ex = is_mu ? exmu : exls;
        float4 h = ((const float4*)(g_h23 + (size_t)src * 32))[q];
        fma4(acc, ex, h);
    }
    int total = n * 16;
    if (is_mu) {
        float inv = __frcp_rn(smu);
        float4 bb = ((const float4*)bmu)[q];
        float4 o;
        o.x = fmaf(acc.x, inv, bb.x); o.y = fmaf(acc.y, inv, bb.y);
        o.z = fmaf(acc.z, inv, bb.z); o.w = fmaf(acc.w, inv, bb.w);
        ((float4*)out)[node * 4 + q] = o;
    } else {
        float inv = __frcp_rn(sls);
        float4 bb = ((const float4*)bls)[q - 4];
        float4 o;
        o.x = fmaf(acc.x, inv, bb.x); o.y = fmaf(acc.y, inv, bb.y);
        o.z = fmaf(acc.z, inv, bb.z); o.w = fmaf(acc.w, inv, bb.w);
        ((float4*)(out + total))[node * 4 + (q - 4)] = o;
    }
}

// ---------------- launch ---------------------------------------------
extern "C" void kernel_launch(void* const* d_in, const int* in_sizes, int n_in,
                              void* d_out, int out_size)
{
    const float* x    = (const float*)d_in[0];
    const void*  ei   = d_in[1];
    const float* W1   = (const float*)d_in[2];
    const float* a1s  = (const float*)d_in[3];
    const float* a1d  = (const float*)d_in[4];
    const float* b1   = (const float*)d_in[5];
    const float* Wmu  = (const float*)d_in[6];
    const float* amus = (const float*)d_in[7];
    const float* amud = (const float*)d_in[8];
    const float* bmu  = (const float*)d_in[9];
    const float* Wls  = (const float*)d_in[10];
    const float* alss = (const float*)d_in[11];
    const float* alsd = (const float*)d_in[12];
    const float* bls  = (const float*)d_in[13];

    int n     = in_sizes[0] / 128;      // 100000
    int emain = in_sizes[1] / 2;        // 1600000
    int etot  = emain + n;
    int nblk  = (n + 1023) / 1024;      // scan blocks
    float* out = (float*)d_out;

    k_detect<<<1, 256>>>((const unsigned int*)ei, emain);
    k_zerodeg<<<512, 256>>>(n);
    k_prep<<<2048, 256>>>(ei, emain, n);
    k_gemm1<<<(n + 63) / 64, 256>>>(x, W1, a1s, a1d, n);
    k_scanA<<<nblk, 256>>>(n);
    k_scanB<<<1, 128>>>(nblk);
    k_scanC<<<nblk, 256>>>(n, etot);
    k_scatter<<<(etot + 255) / 256, 256>>>(etot);
    k_gather1<<<(n * 8 + 255) / 256, 256>>>(b1, Wmu, amus, amud,
                                            Wls, alss, alsd, n);
    k_gather23<<<(n * 8 + 255) / 256, 256>>>(bmu, bls, out, n);
}

// round 10
// speedup vs baseline: 1.0657x; 1.0657x over previous
#include <cuda_runtime.h>
#include <cuda_fp16.h>

// ---------------- problem constants (from reference) ----------------
#define NMAX   100000
#define EMAX   1700032
#define NEG_SLOPE 0.2f

__device__ __forceinline__ void fma4(float4& acc, float s, const float4& wv) {
    acc.x = fmaf(s, wv.x, acc.x); acc.y = fmaf(s, wv.y, acc.y);
    acc.z = fmaf(s, wv.z, acc.z); acc.w = fmaf(s, wv.w, acc.w);
}
__device__ __forceinline__ float lrelu(float v) {
    return (v > 0.0f) ? v : NEG_SLOPE * v;
}
// pack float4 -> 4 fp16 in a uint2
__device__ __forceinline__ uint2 pack_h4(const float4& v) {
    __half2 p0 = __floats2half2_rn(v.x, v.y);
    __half2 p1 = __floats2half2_rn(v.z, v.w);
    uint2 u;
    u.x = *reinterpret_cast<const unsigned int*>(&p0);
    u.y = *reinterpret_cast<const unsigned int*>(&p1);
    return u;
}
// unpack uint2 (4 fp16) and fma into float4 acc with scalar s
__device__ __forceinline__ void fma4_h(float4& acc, float s, uint2 u) {
    __half2 p0 = *reinterpret_cast<const __half2*>(&u.x);
    __half2 p1 = *reinterpret_cast<const __half2*>(&u.y);
    float2 f0 = __half22float2(p0);
    float2 f1 = __half22float2(p1);
    acc.x = fmaf(s, f0.x, acc.x); acc.y = fmaf(s, f0.y, acc.y);
    acc.z = fmaf(s, f1.x, acc.z); acc.w = fmaf(s, f1.y, acc.w);
}

// ---------------- scratch (device globals) --------------------------
__device__ __align__(16) uint2 g_hlin1h[NMAX * 8];   // x@W1, fp16 rows
__device__ float g_as1[NMAX];
__device__ float g_ad1[NMAX];

__device__ __align__(16) uint2 g_h23h[NMAX * 8];     // interleaved mu|ls, fp16
__device__ __align__(8)  float g_src23[NMAX * 2];
__device__ __align__(8)  float g_dst23[NMAX * 2];

__device__ __align__(8)  int2  g_edges[EMAX];
__device__ int   g_deg[NMAX];
__device__ int   g_off[NMAX + 1];
__device__ int   g_cur[NMAX];
__device__ int   g_bsum[128];
__device__ int   g_csr[EMAX];        // src ids grouped by dst
__device__ int   g_is64;

// ---------------- CSR build -----------------------------------------

__global__ void k_detect(const unsigned int* __restrict__ p, int emain) {
    __shared__ int bad;
    if (threadIdx.x == 0) bad = 0;
    __syncthreads();
    int cnt = 2 * emain; if (cnt > 8192) cnt = 8192;
    for (int i = 1 + 2 * threadIdx.x; i < cnt; i += 2 * blockDim.x)
        if (p[i] != 0u) bad = 1;
    __syncthreads();
    if (threadIdx.x == 0) g_is64 = bad ? 0 : 1;
}

__global__ __launch_bounds__(256) void k_zerodeg(int n) {
    int i = blockIdx.x * blockDim.x + threadIdx.x;
    int stride = gridDim.x * blockDim.x;
    for (int j = i; j < n; j += stride) g_deg[j] = 0;
}

// decode edges (+ self loops) AND accumulate degree histogram
__global__ __launch_bounds__(256) void k_prep(const void* __restrict__ ei,
                                              int emain, int n) {
    int etot = emain + n;
    int stride = gridDim.x * blockDim.x;
    int tid0 = blockIdx.x * blockDim.x + threadIdx.x;
    int is64 = g_is64;
    for (int e = tid0; e < etot; e += stride) {
        int s, d;
        if (e >= emain) { s = d = e - emain; }
        else if (is64) {
            const long long* p = (const long long*)ei;
            s = (int)p[e]; d = (int)p[emain + e];
        } else {
            const int* p = (const int*)ei;
            s = p[e]; d = p[emain + e];
        }
        g_edges[e] = make_int2(s, d);
        atomicAdd(&g_deg[d], 1);
    }
}

// block-level exclusive scan: 1024 elems/block, 4/thread
__global__ __launch_bounds__(256) void k_scanA(int n) {
    __shared__ int ts[256];
    int b = blockIdx.x, tid = threadIdx.x;
    int base = b * 1024 + tid * 4;
    int v0 = (base + 0 < n) ? g_deg[base + 0] : 0;
    int v1 = (base + 1 < n) ? g_deg[base + 1] : 0;
    int v2 = (base + 2 < n) ? g_deg[base + 2] : 0;
    int v3 = (base + 3 < n) ? g_deg[base + 3] : 0;
    int tsum = v0 + v1 + v2 + v3;
    ts[tid] = tsum;
    __syncthreads();
    #pragma unroll
    for (int d = 1; d < 256; d <<= 1) {
        int t = (tid >= d) ? ts[tid - d] : 0;
        __syncthreads();
        ts[tid] += t;
        __syncthreads();
    }
    int excl = (tid > 0) ? ts[tid - 1] : 0;
    int run = excl;
    if (base + 0 < n) { g_off[base + 0] = run; } run += v0;
    if (base + 1 < n) { g_off[base + 1] = run; } run += v1;
    if (base + 2 < n) { g_off[base + 2] = run; } run += v2;
    if (base + 3 < n) { g_off[base + 3] = run; } run += v3;
    if (tid == 255) g_bsum[b] = ts[255];
}

__global__ void k_scanB(int nblk) {
    __shared__ int s[128];
    int tid = threadIdx.x;
    s[tid] = (tid < nblk) ? g_bsum[tid] : 0;
    __syncthreads();
    #pragma unroll
    for (int d = 1; d < 128; d <<= 1) {
        int t = (tid >= d) ? s[tid - d] : 0;
        __syncthreads();
        s[tid] += t;
        __syncthreads();
    }
    if (tid < nblk) g_bsum[tid] = (tid > 0) ? s[tid - 1] : 0;
}

__global__ __launch_bounds__(256) void k_scanC(int n, int etot) {
    int b = blockIdx.x, tid = threadIdx.x;
    int add = g_bsum[b];
    int base = b * 1024 + tid * 4;
    #pragma unroll
    for (int j = 0; j < 4; j++) {
        int i = base + j;
        if (i < n) {
            int v = g_off[i] + add;
            g_off[i] = v;
            g_cur[i] = v;
        }
    }
    if (b == 0 && tid == 0) g_off[n] = etot;
}

__global__ __launch_bounds__(256) void k_scatter(int etot) {
    int stride = gridDim.x * blockDim.x;
    for (int e = blockIdx.x * blockDim.x + threadIdx.x; e < etot; e += stride) {
        int2 ed = g_edges[e];
        int pos = atomicAdd(&g_cur[ed.y], 1);
        g_csr[pos] = ed.x;
    }
}

// ---------------- compute kernels -----------------------------------

// hlin1 = x @ W1 ; attention dots. 64 nodes/block, 2 nodes/thread,
// x staged in smem (R8 layout — fastest measured).
__global__ __launch_bounds__(256) void k_gemm1(
    const float* __restrict__ x, const float* __restrict__ W1,
    const float* __restrict__ a1s, const float* __restrict__ a1d, int n)
{
    __shared__ float4 Ws4[128 * 8];
    __shared__ float4 xs4[64 * 33];
    __shared__ float4 as4[8], ad4[8];
    int tid = threadIdx.x;
    const float4* W4 = (const float4*)W1;
    for (int i = tid; i < 1024; i += 256) Ws4[i] = W4[i];
    if (tid < 8)        as4[tid]     = ((const float4*)a1s)[tid];
    else if (tid < 16)  ad4[tid - 8] = ((const float4*)a1d)[tid - 8];

    int base = blockIdx.x * 64;
    const float4* xg = (const float4*)x + (size_t)base * 32;
    int navail = n - base; if (navail > 64) navail = 64;
    for (int f = tid; f < navail * 32; f += 256) {
        int node = f >> 5, j = f & 31;
        xs4[node * 33 + j] = xg[f];
    }
    __syncthreads();

    int warp = tid >> 5, lane = tid & 31;
    int pair = lane >> 3, q = lane & 7;
    int nodeL0 = warp * 8 + pair * 2;
    int nodeL1 = nodeL0 + 1;
    int node0 = base + nodeL0, node1 = base + nodeL1;

    const float4* xr0 = xs4 + nodeL0 * 33;
    const float4* xr1 = xs4 + nodeL1 * 33;
    float4 acc0 = make_float4(0.f, 0.f, 0.f, 0.f);
    float4 acc1 = make_float4(0.f, 0.f, 0.f, 0.f);
    #pragma unroll 2
    for (int k4 = 0; k4 < 32; k4++) {
        float4 xv0 = xr0[k4];
        float4 xv1 = xr1[k4];
        float4 w0 = Ws4[(k4 * 4 + 0) * 8 + q];
        float4 w1 = Ws4[(k4 * 4 + 1) * 8 + q];
        float4 w2 = Ws4[(k4 * 4 + 2) * 8 + q];
        float4 w3 = Ws4[(k4 * 4 + 3) * 8 + q];
        fma4(acc0, xv0.x, w0); fma4(acc1, xv1.x, w0);
        fma4(acc0, xv0.y, w1); fma4(acc1, xv1.y, w1);
        fma4(acc0, xv0.z, w2); fma4(acc1, xv1.z, w2);
        fma4(acc0, xv0.w, w3); fma4(acc1, xv1.w, w3);
    }

    float4 av = as4[q], dv = ad4[q];
    float ts0 = acc0.x * av.x + acc0.y * av.y + acc0.z * av.z + acc0.w * av.w;
    float td0 = acc0.x * dv.x + acc0.y * dv.y + acc0.z * dv.z + acc0.w * dv.w;
    float ts1 = acc1.x * av.x + acc1.y * av.y + acc1.z * av.z + acc1.w * av.w;
    float td1 = acc1.x * dv.x + acc1.y * dv.y + acc1.z * dv.z + acc1.w * dv.w;
    #pragma unroll
    for (int off = 4; off >= 1; off >>= 1) {
        ts0 += __shfl_xor_sync(0xffffffffu, ts0, off);
        td0 += __shfl_xor_sync(0xffffffffu, td0, off);
        ts1 += __shfl_xor_sync(0xffffffffu, ts1, off);
        td1 += __shfl_xor_sync(0xffffffffu, td1, off);
    }
    if (node0 < n) {
        g_hlin1h[node0 * 8 + q] = pack_h4(acc0);
        if (q == 0) { g_as1[node0] = ts0; g_ad1[node0] = td0; }
    }
    if (node1 < n) {
        g_hlin1h[node1 * 8 + q] = pack_h4(acc1);
        if (q == 0) { g_as1[node1] = ts1; g_ad1[node1] = td1; }
    }
}

// Fused layer-1 gather + layer-2 linear (fp16 h rows, fp32 accum).
__global__ __launch_bounds__(256) void k_gather1(
    const float* __restrict__ b1,
    const float* __restrict__ Wmu, const float* __restrict__ amus,
    const float* __restrict__ amud,
    const float* __restrict__ Wls, const float* __restrict__ alss,
    const float* __restrict__ alsd, int n)
{
    __shared__ float Wcat[32 * 32];      // [k][c]: c<16 mu, c>=16 ls
    __shared__ float4 b1s4[8];
    __shared__ float4 srcv4[8], dstv4[8];
    int tid = threadIdx.x;
    for (int i = tid; i < 1024; i += 256) {
        int k = i >> 5, c = i & 31;
        Wcat[i] = (c < 16) ? Wmu[k * 16 + c] : Wls[k * 16 + (c - 16)];
    }
    if (tid < 8) b1s4[tid] = ((const float4*)b1)[tid];
    if (tid < 32) {
        float sv = (tid < 16) ? amus[tid] : alss[tid - 16];
        float dv = (tid < 16) ? amud[tid] : alsd[tid - 16];
        ((float*)srcv4)[tid] = sv;
        ((float*)dstv4)[tid] = dv;
    }
    __syncthreads();

    int t = blockIdx.x * blockDim.x + tid;
    int node = t >> 3;
    bool act = (node < n);
    if (!act) node = n - 1;
    int lane = tid & 31;
    int q = lane & 7;
    int gbase = lane & 24;

    float ad = g_ad1[node];
    int off0 = g_off[node], off1 = g_off[node + 1];
    float4 acc = make_float4(0.f, 0.f, 0.f, 0.f);
    float s = 0.0f;
    #pragma unroll 4
    for (int i = off0; i < off1; i++) {
        int src = g_csr[i];
        float ex = __expf(lrelu(g_as1[src] + ad));
        uint2 hv = g_hlin1h[src * 8 + q];
        fma4_h(acc, ex, hv);
        s += ex;
    }
    float inv = __frcp_rn(s);
    float4 bb = b1s4[q];
    float4 h1;
    h1.x = fmaxf(fmaf(acc.x, inv, bb.x), 0.f);
    h1.y = fmaxf(fmaf(acc.y, inv, bb.y), 0.f);
    h1.z = fmaxf(fmaf(acc.z, inv, bb.z), 0.f);
    h1.w = fmaxf(fmaf(acc.w, inv, bb.w), 0.f);

    // 32x32 matmul: shuffle-broadcast h1 across the 8-lane group.
    const float4* Wc4 = (const float4*)Wcat;
    float4 o = make_float4(0.f, 0.f, 0.f, 0.f);
    #pragma unroll
    for (int r = 0; r < 8; r++) {
        float hx = __shfl_sync(0xffffffffu, h1.x, gbase + r);
        float hy = __shfl_sync(0xffffffffu, h1.y, gbase + r);
        float hz = __shfl_sync(0xffffffffu, h1.z, gbase + r);
        float hw = __shfl_sync(0xffffffffu, h1.w, gbase + r);
        fma4(o, hx, Wc4[(4 * r + 0) * 8 + q]);
        fma4(o, hy, Wc4[(4 * r + 1) * 8 + q]);
        fma4(o, hz, Wc4[(4 * r + 2) * 8 + q]);
        fma4(o, hw, Wc4[(4 * r + 3) * 8 + q]);
    }

    float4 av = srcv4[q], dv = dstv4[q];
    float ts = o.x * av.x + o.y * av.y + o.z * av.z + o.w * av.w;
    float td = o.x * dv.x + o.y * dv.y + o.z * dv.z + o.w * dv.w;
    #pragma unroll
    for (int off = 2; off >= 1; off >>= 1) {
        ts += __shfl_xor_sync(0xffffffffu, ts, off);
        td += __shfl_xor_sync(0xffffffffu, td, off);
    }
    if (act) {
        g_h23h[node * 8 + q] = pack_h4(o);
        if (q == 0) { g_src23[2 * node + 0] = ts; g_dst23[2 * node + 0] = td; }
        if (q == 4) { g_src23[2 * node + 1] = ts; g_dst23[2 * node + 1] = td; }
    }
}

// Layer-2 gather (mu+ls fused, fp16 h rows): writes final output.
__global__ __launch_bounds__(256) void k_gather23(
    const float* __restrict__ bmu, const float* __restrict__ bls,
    float* __restrict__ out, int n)
{
    int t = blockIdx.x * blockDim.x + threadIdx.x;
    int node = t >> 3;
    if (node >= n) return;
    int q = t & 7;
    float2 dv = *(const float2*)(g_dst23 + 2 * node);
    int off0 = g_off[node], off1 = g_off[node + 1];
    float4 acc = make_float4(0.f, 0.f, 0.f, 0.f);
    float smu = 0.0f, sls = 0.0f;
    bool is_mu = (q < 4);
    #pragma unroll 4
    for (int i = off0; i < off1; i++) {
        int src = g_csr[i];
        float2 sv = *(const float2*)(g_src23 + 2 * src);
        float exmu = __expf(lrelu(sv.x + dv.x));
        float exls = __expf(lrelu(sv.y + dv.y));
        smu += exmu; sls += exls;
        float ex = is_mu ? exmu : exls;
        uint2 hv = g_h23h[src * 8 + q];
        fma4_h(acc, ex, hv);
    }
    int total = n * 16;
    if (is_mu) {
        float inv = __frcp_rn(smu);
        float4 bb = ((const float4*)bmu)[q];
        float4 o;
        o.x = fmaf(acc.x, inv, bb.x); o.y = fmaf(acc.y, inv, bb.y);
        o.z = fmaf(acc.z, inv, bb.z); o.w = fmaf(acc.w, inv, bb.w);
        ((float4*)out)[node * 4 + q] = o;
    } else {
        float inv = __frcp_rn(sls);
        float4 bb = ((const float4*)bls)[q - 4];
        float4 o;
        o.x = fmaf(acc.x, inv, bb.x); o.y = fmaf(acc.y, inv, bb.y);
        o.z = fmaf(acc.z, inv, bb.z); o.w = fmaf(acc.w, inv, bb.w);
        ((float4*)(out + total))[node * 4 + (q - 4)] = o;
    }
}

// ---------------- launch ---------------------------------------------
extern "C" void kernel_launch(void* const* d_in, const int* in_sizes, int n_in,
                              void* d_out, int out_size)
{
    const float* x    = (const float*)d_in[0];
    const void*  ei   = d_in[1];
    const float* W1   = (const float*)d_in[2];
    const float* a1s  = (const float*)d_in[3];
    const float* a1d  = (const float*)d_in[4];
    const float* b1   = (const float*)d_in[5];
    const float* Wmu  = (const float*)d_in[6];
    const float* amus = (const float*)d_in[7];
    const float* amud = (const float*)d_in[8];
    const float* bmu  = (const float*)d_in[9];
    const float* Wls  = (const float*)d_in[10];
    const float* alss = (const float*)d_in[11];
    const float* alsd = (const float*)d_in[12];
    const float* bls  = (const float*)d_in[13];

    int n     = in_sizes[0] / 128;      // 100000
    int emain = in_sizes[1] / 2;        // 1600000
    int etot  = emain + n;
    int nblk  = (n + 1023) / 1024;      // scan blocks
    float* out = (float*)d_out;

    k_detect<<<1, 256>>>((const unsigned int*)ei, emain);
    k_zerodeg<<<512, 256>>>(n);
    k_prep<<<2048, 256>>>(ei, emain, n);
    k_gemm1<<<(n + 63) / 64, 256>>>(x, W1, a1s, a1d, n);
    k_scanA<<<nblk, 256>>>(n);
    k_scanB<<<1, 128>>>(nblk);
    k_scanC<<<nblk, 256>>>(n, etot);
    k_scatter<<<(etot + 255) / 256, 256>>>(etot);
    k_gather1<<<(n * 8 + 255) / 256, 256>>>(b1, Wmu, amus, amud,
                                            Wls, alss, alsd, n);
    k_gather23<<<(n * 8 + 255) / 256, 256>>>(bmu, bls, out, n);
}

// round 11
// speedup vs baseline: 1.1108x; 1.0423x over previous
#include <cuda_runtime.h>
#include <cuda_fp16.h>

// ---------------- problem constants (from reference) ----------------
#define NMAX   100000
#define EMAX   1700032
#define NEG_SLOPE 0.2f

__device__ __forceinline__ void fma4(float4& acc, float s, const float4& wv) {
    acc.x = fmaf(s, wv.x, acc.x); acc.y = fmaf(s, wv.y, acc.y);
    acc.z = fmaf(s, wv.z, acc.z); acc.w = fmaf(s, wv.w, acc.w);
}
__device__ __forceinline__ float lrelu(float v) {
    return (v > 0.0f) ? v : NEG_SLOPE * v;
}
__device__ __forceinline__ uint2 pack_h4(const float4& v) {
    __half2 p0 = __floats2half2_rn(v.x, v.y);
    __half2 p1 = __floats2half2_rn(v.z, v.w);
    uint2 u;
    u.x = *reinterpret_cast<const unsigned int*>(&p0);
    u.y = *reinterpret_cast<const unsigned int*>(&p1);
    return u;
}
__device__ __forceinline__ void fma4_h(float4& acc, float s, uint2 u) {
    __half2 p0 = *reinterpret_cast<const __half2*>(&u.x);
    __half2 p1 = *reinterpret_cast<const __half2*>(&u.y);
    float2 f0 = __half22float2(p0);
    float2 f1 = __half22float2(p1);
    acc.x = fmaf(s, f0.x, acc.x); acc.y = fmaf(s, f0.y, acc.y);
    acc.z = fmaf(s, f1.x, acc.z); acc.w = fmaf(s, f1.y, acc.w);
}

// ---------------- scratch (device globals) --------------------------
__device__ __align__(16) uint2 g_hlin1h[NMAX * 8];   // x@W1, fp16 rows
__device__ float g_as1[NMAX];
__device__ float g_ad1[NMAX];

__device__ __align__(16) uint2 g_h23h[NMAX * 8];     // interleaved mu|ls, fp16
__device__ __align__(8)  float g_src23[NMAX * 2];
__device__ __align__(8)  float g_dst23[NMAX * 2];

__device__ int   g_deg[NMAX];
__device__ int   g_off[NMAX + 1];
__device__ int   g_cur[NMAX];
__device__ int   g_bsum[128];
__device__ int   g_csr[EMAX];        // src ids grouped by dst
__device__ int   g_is64;

// ---------------- CSR build -----------------------------------------

__global__ void k_detect(const unsigned int* __restrict__ p, int emain) {
    __shared__ int bad;
    if (threadIdx.x == 0) bad = 0;
    __syncthreads();
    int cnt = 2 * emain; if (cnt > 8192) cnt = 8192;
    for (int i = 1 + 2 * threadIdx.x; i < cnt; i += 2 * blockDim.x)
        if (p[i] != 0u) bad = 1;
    __syncthreads();
    if (threadIdx.x == 0) g_is64 = bad ? 0 : 1;
}

// deg starts at 1: the self loop
__global__ __launch_bounds__(256) void k_deginit(int n) {
    int i = blockIdx.x * blockDim.x + threadIdx.x;
    int stride = gridDim.x * blockDim.x;
    for (int j = i; j < n; j += stride) g_deg[j] = 1;
}

// histogram straight from the raw dst half of edge_index
__global__ __launch_bounds__(256) void k_hist(const void* __restrict__ ei,
                                              int emain) {
    int stride = gridDim.x * blockDim.x;
    int is64 = g_is64;
    for (int e = blockIdx.x * blockDim.x + threadIdx.x; e < emain; e += stride) {
        int d = is64 ? (int)((const long long*)ei)[emain + e]
                     : ((const int*)ei)[emain + e];
        atomicAdd(&g_deg[d], 1);
    }
}

// block-level exclusive scan: 1024 elems/block, 4/thread
__global__ __launch_bounds__(256) void k_scanA(int n) {
    __shared__ int ts[256];
    int b = blockIdx.x, tid = threadIdx.x;
    int base = b * 1024 + tid * 4;
    int v0 = (base + 0 < n) ? g_deg[base + 0] : 0;
    int v1 = (base + 1 < n) ? g_deg[base + 1] : 0;
    int v2 = (base + 2 < n) ? g_deg[base + 2] : 0;
    int v3 = (base + 3 < n) ? g_deg[base + 3] : 0;
    int tsum = v0 + v1 + v2 + v3;
    ts[tid] = tsum;
    __syncthreads();
    #pragma unroll
    for (int d = 1; d < 256; d <<= 1) {
        int t = (tid >= d) ? ts[tid - d] : 0;
        __syncthreads();
        ts[tid] += t;
        __syncthreads();
    }
    int excl = (tid > 0) ? ts[tid - 1] : 0;
    int run = excl;
    if (base + 0 < n) { g_off[base + 0] = run; } run += v0;
    if (base + 1 < n) { g_off[base + 1] = run; } run += v1;
    if (base + 2 < n) { g_off[base + 2] = run; } run += v2;
    if (base + 3 < n) { g_off[base + 3] = run; } run += v3;
    if (tid == 255) g_bsum[b] = ts[255];
}

__global__ void k_scanB(int nblk) {
    __shared__ int s[128];
    int tid = threadIdx.x;
    s[tid] = (tid < nblk) ? g_bsum[tid] : 0;
    __syncthreads();
    #pragma unroll
    for (int d = 1; d < 128; d <<= 1) {
        int t = (tid >= d) ? s[tid - d] : 0;
        __syncthreads();
        s[tid] += t;
        __syncthreads();
    }
    if (tid < nblk) g_bsum[tid] = (tid > 0) ? s[tid - 1] : 0;
}

__global__ __launch_bounds__(256) void k_scanC(int n, int etot) {
    int b = blockIdx.x, tid = threadIdx.x;
    int add = g_bsum[b];
    int base = b * 1024 + tid * 4;
    #pragma unroll
    for (int j = 0; j < 4; j++) {
        int i = base + j;
        if (i < n) {
            int v = g_off[i] + add;
            g_off[i] = v;
            g_cur[i] = v;
        }
    }
    if (b == 0 && tid == 0) g_off[n] = etot;
}

// scatter straight from the raw edge_index (+ self loops)
__global__ __launch_bounds__(256) void k_scatter(const void* __restrict__ ei,
                                                 int emain, int n) {
    int etot = emain + n;
    int stride = gridDim.x * blockDim.x;
    int is64 = g_is64;
    for (int e = blockIdx.x * blockDim.x + threadIdx.x; e < etot; e += stride) {
        int s, d;
        if (e >= emain) { s = d = e - emain; }
        else if (is64) {
            const long long* p = (const long long*)ei;
            s = (int)p[e]; d = (int)p[emain + e];
        } else {
            const int* p = (const int*)ei;
            s = p[e]; d = p[emain + e];
        }
        int pos = atomicAdd(&g_cur[d], 1);
        g_csr[pos] = s;
    }
}

// ---------------- compute kernels -----------------------------------

// hlin1 = x @ W1 ; attention dots. 64 nodes/block, 128 threads,
// 4 nodes/thread (16 independent FFMA chains for latency cover).
__global__ __launch_bounds__(128) void k_gemm1(
    const float* __restrict__ x, const float* __restrict__ W1,
    const float* __restrict__ a1s, const float* __restrict__ a1d, int n)
{
    __shared__ float4 Ws4[128 * 8];    // [k][q]
    __shared__ float4 xs4[64 * 33];    // 64 nodes x (32 float4 + pad)
    __shared__ float4 as4[8], ad4[8];
    int tid = threadIdx.x;
    const float4* W4 = (const float4*)W1;
    for (int i = tid; i < 1024; i += 128) Ws4[i] = W4[i];
    if (tid < 8)        as4[tid]     = ((const float4*)a1s)[tid];
    else if (tid < 16)  ad4[tid - 8] = ((const float4*)a1d)[tid - 8];

    int base = blockIdx.x * 64;
    const float4* xg = (const float4*)x + (size_t)base * 32;
    int navail = n - base; if (navail > 64) navail = 64;
    for (int f = tid; f < navail * 32; f += 128) {
        xs4[(f >> 5) * 33 + (f & 31)] = xg[f];
    }
    __syncthreads();

    int warp = tid >> 5, lane = tid & 31;
    int pair = lane >> 3, q = lane & 7;
    int nb = warp * 16 + pair;         // nodes nb, nb+4, nb+8, nb+12

    float4 acc0 = make_float4(0.f, 0.f, 0.f, 0.f);
    float4 acc1 = make_float4(0.f, 0.f, 0.f, 0.f);
    float4 acc2 = make_float4(0.f, 0.f, 0.f, 0.f);
    float4 acc3 = make_float4(0.f, 0.f, 0.f, 0.f);
    #pragma unroll 2
    for (int k4 = 0; k4 < 32; k4++) {
        float4 w0 = Ws4[(k4 * 4 + 0) * 8 + q];
        float4 w1 = Ws4[(k4 * 4 + 1) * 8 + q];
        float4 w2 = Ws4[(k4 * 4 + 2) * 8 + q];
        float4 w3 = Ws4[(k4 * 4 + 3) * 8 + q];
        float4 xv0 = xs4[(nb + 0)  * 33 + k4];
        float4 xv1 = xs4[(nb + 4)  * 33 + k4];
        float4 xv2 = xs4[(nb + 8)  * 33 + k4];
        float4 xv3 = xs4[(nb + 12) * 33 + k4];
        fma4(acc0, xv0.x, w0); fma4(acc1, xv1.x, w0);
        fma4(acc2, xv2.x, w0); fma4(acc3, xv3.x, w0);
        fma4(acc0, xv0.y, w1); fma4(acc1, xv1.y, w1);
        fma4(acc2, xv2.y, w1); fma4(acc3, xv3.y, w1);
        fma4(acc0, xv0.z, w2); fma4(acc1, xv1.z, w2);
        fma4(acc2, xv2.z, w2); fma4(acc3, xv3.z, w2);
        fma4(acc0, xv0.w, w3); fma4(acc1, xv1.w, w3);
        fma4(acc2, xv2.w, w3); fma4(acc3, xv3.w, w3);
    }

    float4 av = as4[q], dv = ad4[q];
    float4 accs[4] = {acc0, acc1, acc2, acc3};
    #pragma unroll
    for (int j = 0; j < 4; j++) {
        int node = base + nb + 4 * j;
        float4 a = accs[j];
        float ts = a.x * av.x + a.y * av.y + a.z * av.z + a.w * av.w;
        float td = a.x * dv.x + a.y * dv.y + a.z * dv.z + a.w * dv.w;
        #pragma unroll
        for (int off = 4; off >= 1; off >>= 1) {
            ts += __shfl_xor_sync(0xffffffffu, ts, off);
            td += __shfl_xor_sync(0xffffffffu, td, off);
        }
        if (node < n) {
            g_hlin1h[node * 8 + q] = pack_h4(a);
            if (q == 0) { g_as1[node] = ts; g_ad1[node] = td; }
        }
    }
}

// Fused layer-1 gather + layer-2 linear (fp16 h rows, fp32 accum).
__global__ __launch_bounds__(256) void k_gather1(
    const float* __restrict__ b1,
    const float* __restrict__ Wmu, const float* __restrict__ amus,
    const float* __restrict__ amud,
    const float* __restrict__ Wls, const float* __restrict__ alss,
    const float* __restrict__ alsd, int n)
{
    __shared__ float Wcat[32 * 32];      // [k][c]: c<16 mu, c>=16 ls
    __shared__ float4 b1s4[8];
    __shared__ float4 srcv4[8], dstv4[8];
    int tid = threadIdx.x;
    for (int i = tid; i < 1024; i += 256) {
        int k = i >> 5, c = i & 31;
        Wcat[i] = (c < 16) ? Wmu[k * 16 + c] : Wls[k * 16 + (c - 16)];
    }
    if (tid < 8) b1s4[tid] = ((const float4*)b1)[tid];
    if (tid < 32) {
        float sv = (tid < 16) ? amus[tid] : alss[tid - 16];
        float dv = (tid < 16) ? amud[tid] : alsd[tid - 16];
        ((float*)srcv4)[tid] = sv;
        ((float*)dstv4)[tid] = dv;
    }
    __syncthreads();

    int t = blockIdx.x * blockDim.x + tid;
    int node = t >> 3;
    bool act = (node < n);
    if (!act) node = n - 1;
    int lane = tid & 31;
    int q = lane & 7;
    int gbase = lane & 24;

    float ad = g_ad1[node];
    int off0 = g_off[node], off1 = g_off[node + 1];
    float4 acc = make_float4(0.f, 0.f, 0.f, 0.f);
    float s = 0.0f;
    #pragma unroll 4
    for (int i = off0; i < off1; i++) {
        int src = g_csr[i];
        float ex = __expf(lrelu(g_as1[src] + ad));
        uint2 hv = g_hlin1h[src * 8 + q];
        fma4_h(acc, ex, hv);
        s += ex;
    }
    float inv = __frcp_rn(s);
    float4 bb = b1s4[q];
    float4 h1;
    h1.x = fmaxf(fmaf(acc.x, inv, bb.x), 0.f);
    h1.y = fmaxf(fmaf(acc.y, inv, bb.y), 0.f);
    h1.z = fmaxf(fmaf(acc.z, inv, bb.z), 0.f);
    h1.w = fmaxf(fmaf(acc.w, inv, bb.w), 0.f);

    // 32x32 matmul: shuffle-broadcast h1 across the 8-lane group.
    const float4* Wc4 = (const float4*)Wcat;
    float4 o = make_float4(0.f, 0.f, 0.f, 0.f);
    #pragma unroll
    for (int r = 0; r < 8; r++) {
        float hx = __shfl_sync(0xffffffffu, h1.x, gbase + r);
        float hy = __shfl_sync(0xffffffffu, h1.y, gbase + r);
        float hz = __shfl_sync(0xffffffffu, h1.z, gbase + r);
        float hw = __shfl_sync(0xffffffffu, h1.w, gbase + r);
        fma4(o, hx, Wc4[(4 * r + 0) * 8 + q]);
        fma4(o, hy, Wc4[(4 * r + 1) * 8 + q]);
        fma4(o, hz, Wc4[(4 * r + 2) * 8 + q]);
        fma4(o, hw, Wc4[(4 * r + 3) * 8 + q]);
    }

    float4 av = srcv4[q], dv = dstv4[q];
    float ts = o.x * av.x + o.y * av.y + o.z * av.z + o.w * av.w;
    float td = o.x * dv.x + o.y * dv.y + o.z * dv.z + o.w * dv.w;
    #pragma unroll
    for (int off = 2; off >= 1; off >>= 1) {
        ts += __shfl_xor_sync(0xffffffffu, ts, off);
        td += __shfl_xor_sync(0xffffffffu, td, off);
    }
    if (act) {
        g_h23h[node * 8 + q] = pack_h4(o);
        if (q == 0) { g_src23[2 * node + 0] = ts; g_dst23[2 * node + 0] = td; }
        if (q == 4) { g_src23[2 * node + 1] = ts; g_dst23[2 * node + 1] = td; }
    }
}

// Layer-2 gather (mu+ls fused, fp16 h rows): writes final output.
__global__ __launch_bounds__(256) void k_gather23(
    const float* __restrict__ bmu, const float* __restrict__ bls,
    float* __restrict__ out, int n)
{
    int t = blockIdx.x * blockDim.x + threadIdx.x;
    int node = t >> 3;
    if (node >= n) return;
    int q = t & 7;
    float2 dv = *(const float2*)(g_dst23 + 2 * node);
    int off0 = g_off[node], off1 = g_off[node + 1];
    float4 acc = make_float4(0.f, 0.f, 0.f, 0.f);
    float smu = 0.0f, sls = 0.0f;
    bool is_mu = (q < 4);
    #pragma unroll 4
    for (int i = off0; i < off1; i++) {
        int src = g_csr[i];
        float2 sv = *(const float2*)(g_src23 + 2 * src);
        float exmu = __expf(lrelu(sv.x + dv.x));
        float exls = __expf(lrelu(sv.y + dv.y));
        smu += exmu; sls += exls;
        float ex = is_mu ? exmu : exls;
        uint2 hv = g_h23h[src * 8 + q];
        fma4_h(acc, ex, hv);
    }
    int total = n * 16;
    if (is_mu) {
        float inv = __frcp_rn(smu);
        float4 bb = ((const float4*)bmu)[q];
        float4 o;
        o.x = fmaf(acc.x, inv, bb.x); o.y = fmaf(acc.y, inv, bb.y);
        o.z = fmaf(acc.z, inv, bb.z); o.w = fmaf(acc.w, inv, bb.w);
        ((float4*)out)[node * 4 + q] = o;
    } else {
        float inv = __frcp_rn(sls);
        float4 bb = ((const float4*)bls)[q - 4];
        float4 o;
        o.x = fmaf(acc.x, inv, bb.x); o.y = fmaf(acc.y, inv, bb.y);
        o.z = fmaf(acc.z, inv, bb.z); o.w = fmaf(acc.w, inv, bb.w);
        ((float4*)(out + total))[node * 4 + (q - 4)] = o;
    }
}

// ---------------- launch ---------------------------------------------
extern "C" void kernel_launch(void* const* d_in, const int* in_sizes, int n_in,
                              void* d_out, int out_size)
{
    const float* x    = (const float*)d_in[0];
    const void*  ei   = d_in[1];
    const float* W1   = (const float*)d_in[2];
    const float* a1s  = (const float*)d_in[3];
    const float* a1d  = (const float*)d_in[4];
    const float* b1   = (const float*)d_in[5];
    const float* Wmu  = (const float*)d_in[6];
    const float* amus = (const float*)d_in[7];
    const float* amud = (const float*)d_in[8];
    const float* bmu  = (const float*)d_in[9];
    const float* Wls  = (const float*)d_in[10];
    const float* alss = (const float*)d_in[11];
    const float* alsd = (const float*)d_in[12];
    const float* bls  = (const float*)d_in[13];

    int n     = in_sizes[0] / 128;      // 100000
    int emain = in_sizes[1] / 2;        // 1600000
    int etot  = emain + n;
    int nblk  = (n + 1023) / 1024;      // scan blocks
    float* out = (float*)d_out;

    k_detect<<<1, 256>>>((const unsigned int*)ei, emain);
    k_deginit<<<512, 256>>>(n);
    k_hist<<<(emain + 255) / 256, 256>>>(ei, emain);
    k_gemm1<<<(n + 63) / 64, 128>>>(x, W1, a1s, a1d, n);
    k_scanA<<<nblk, 256>>>(n);
    k_scanB<<<1, 128>>>(nblk);
    k_scanC<<<nblk, 256>>>(n, etot);
    k_scatter<<<(etot + 255) / 256, 256>>>(ei, emain, n);
    k_gather1<<<(n * 8 + 255) / 256, 256>>>(b1, Wmu, amus, amud,
                                            Wls, alss, alsd, n);
    k_gather23<<<(n * 8 + 255) / 256, 256>>>(bmu, bls, out, n);
}

// round 13
// speedup vs baseline: 1.1814x; 1.0636x over previous
#include <cuda_runtime.h>
#include <cuda_fp16.h>

// ---------------- problem constants (from reference) ----------------
#define NMAX   100000
#define EMAX   1700032
#define NEG_SLOPE 0.2f

__device__ __forceinline__ void fma4(float4& acc, float s, const float4& wv) {
    acc.x = fmaf(s, wv.x, acc.x); acc.y = fmaf(s, wv.y, acc.y);
    acc.z = fmaf(s, wv.z, acc.z); acc.w = fmaf(s, wv.w, acc.w);
}
__device__ __forceinline__ float lrelu(float v) {
    return (v > 0.0f) ? v : NEG_SLOPE * v;
}
__device__ __forceinline__ uint2 pack_h4(const float4& v) {
    __half2 p0 = __floats2half2_rn(v.x, v.y);
    __half2 p1 = __floats2half2_rn(v.z, v.w);
    uint2 u;
    u.x = *reinterpret_cast<const unsigned int*>(&p0);
    u.y = *reinterpret_cast<const unsigned int*>(&p1);
    return u;
}
__device__ __forceinline__ void fma4_h(float4& acc, float s, uint2 u) {
    __half2 p0 = *reinterpret_cast<const __half2*>(&u.x);
    __half2 p1 = *reinterpret_cast<const __half2*>(&u.y);
    float2 f0 = __half22float2(p0);
    float2 f1 = __half22float2(p1);
    acc.x = fmaf(s, f0.x, acc.x); acc.y = fmaf(s, f0.y, acc.y);
    acc.z = fmaf(s, f1.x, acc.z); acc.w = fmaf(s, f1.y, acc.w);
}

// ---------------- scratch (device globals) --------------------------
__device__ __align__(16) uint2 g_hlin1h[NMAX * 8];   // x@W1, fp16 rows
__device__ float g_as1[NMAX];
__device__ float g_ad1[NMAX];

__device__ __align__(16) uint2 g_h23h[NMAX * 8];     // interleaved mu|ls, fp16
__device__ __align__(8)  float g_src23[NMAX * 2];
__device__ __align__(8)  float g_dst23[NMAX * 2];

__device__ int   g_deg[NMAX];
__device__ int   g_off[NMAX + 1];
__device__ int   g_cur[NMAX];
__device__ int   g_bsum[128];
__device__ int   g_csr[EMAX];        // src ids grouped by dst
__device__ int   g_is64;

// ---------------- CSR build -----------------------------------------

__global__ void k_detect(const unsigned int* __restrict__ p, int emain) {
    __shared__ int bad;
    if (threadIdx.x == 0) bad = 0;
    __syncthreads();
    int cnt = 2 * emain; if (cnt > 8192) cnt = 8192;
    for (int i = 1 + 2 * threadIdx.x; i < cnt; i += 2 * blockDim.x)
        if (p[i] != 0u) bad = 1;
    __syncthreads();
    if (threadIdx.x == 0) g_is64 = bad ? 0 : 1;
}

// deg starts at 1: the self loop
__global__ __launch_bounds__(256) void k_deginit(int n) {
    int i = blockIdx.x * blockDim.x + threadIdx.x;
    int stride = gridDim.x * blockDim.x;
    for (int j = i; j < n; j += stride) g_deg[j] = 1;
}

// histogram straight from the raw dst half of edge_index
__global__ __launch_bounds__(256) void k_hist(const void* __restrict__ ei,
                                              int emain) {
    int stride = gridDim.x * blockDim.x;
    int is64 = g_is64;
    for (int e = blockIdx.x * blockDim.x + threadIdx.x; e < emain; e += stride) {
        int d = is64 ? (int)((const long long*)ei)[emain + e]
                     : ((const int*)ei)[emain + e];
        atomicAdd(&g_deg[d], 1);
    }
}

// block-level exclusive scan: 1024 elems/block, 4/thread
__global__ __launch_bounds__(256) void k_scanA(int n) {
    __shared__ int ts[256];
    int b = blockIdx.x, tid = threadIdx.x;
    int base = b * 1024 + tid * 4;
    int v0 = (base + 0 < n) ? g_deg[base + 0] : 0;
    int v1 = (base + 1 < n) ? g_deg[base + 1] : 0;
    int v2 = (base + 2 < n) ? g_deg[base + 2] : 0;
    int v3 = (base + 3 < n) ? g_deg[base + 3] : 0;
    int tsum = v0 + v1 + v2 + v3;
    ts[tid] = tsum;
    __syncthreads();
    #pragma unroll
    for (int d = 1; d < 256; d <<= 1) {
        int t = (tid >= d) ? ts[tid - d] : 0;
        __syncthreads();
        ts[tid] += t;
        __syncthreads();
    }
    int excl = (tid > 0) ? ts[tid - 1] : 0;
    int run = excl;
    if (base + 0 < n) { g_off[base + 0] = run; } run += v0;
    if (base + 1 < n) { g_off[base + 1] = run; } run += v1;
    if (base + 2 < n) { g_off[base + 2] = run; } run += v2;
    if (base + 3 < n) { g_off[base + 3] = run; } run += v3;
    if (tid == 255) g_bsum[b] = ts[255];
}

__global__ void k_scanB(int nblk) {
    __shared__ int s[128];
    int tid = threadIdx.x;
    s[tid] = (tid < nblk) ? g_bsum[tid] : 0;
    __syncthreads();
    #pragma unroll
    for (int d = 1; d < 128; d <<= 1) {
        int t = (tid >= d) ? s[tid - d] : 0;
        __syncthreads();
        s[tid] += t;
        __syncthreads();
    }
    if (tid < nblk) g_bsum[tid] = (tid > 0) ? s[tid - 1] : 0;
}

__global__ __launch_bounds__(256) void k_scanC(int n, int etot) {
    int b = blockIdx.x, tid = threadIdx.x;
    int add = g_bsum[b];
    int base = b * 1024 + tid * 4;
    #pragma unroll
    for (int j = 0; j < 4; j++) {
        int i = base + j;
        if (i < n) {
            int v = g_off[i] + add;
            g_off[i] = v;
            g_cur[i] = v;
        }
    }
    if (b == 0 && tid == 0) g_off[n] = etot;
}

// scatter straight from the raw edge_index (+ self loops)
__global__ __launch_bounds__(256) void k_scatter(const void* __restrict__ ei,
                                                 int emain, int n) {
    int etot = emain + n;
    int stride = gridDim.x * blockDim.x;
    int is64 = g_is64;
    for (int e = blockIdx.x * blockDim.x + threadIdx.x; e < etot; e += stride) {
        int s, d;
        if (e >= emain) { s = d = e - emain; }
        else if (is64) {
            const long long* p = (const long long*)ei;
            s = (int)p[e]; d = (int)p[emain + e];
        } else {
            const int* p = (const int*)ei;
            s = p[e]; d = p[emain + e];
        }
        int pos = atomicAdd(&g_cur[d], 1);
        g_csr[pos] = s;
    }
}

// ---------------- compute kernels -----------------------------------

// hlin1 = x @ W1 ; attention dots. 64 nodes/block, 128 threads,
// 4 nodes/thread.
__global__ __launch_bounds__(128) void k_gemm1(
    const float* __restrict__ x, const float* __restrict__ W1,
    const float* __restrict__ a1s, const float* __restrict__ a1d, int n)
{
    __shared__ float4 Ws4[128 * 8];    // [k][q]
    __shared__ float4 xs4[64 * 33];    // 64 nodes x (32 float4 + pad)
    __shared__ float4 as4[8], ad4[8];
    int tid = threadIdx.x;
    const float4* W4 = (const float4*)W1;
    for (int i = tid; i < 1024; i += 128) Ws4[i] = W4[i];
    if (tid < 8)        as4[tid]     = ((const float4*)a1s)[tid];
    else if (tid < 16)  ad4[tid - 8] = ((const float4*)a1d)[tid - 8];

    int base = blockIdx.x * 64;
    const float4* xg = (const float4*)x + (size_t)base * 32;
    int navail = n - base; if (navail > 64) navail = 64;
    for (int f = tid; f < navail * 32; f += 128) {
        xs4[(f >> 5) * 33 + (f & 31)] = xg[f];
    }
    __syncthreads();

    int warp = tid >> 5, lane = tid & 31;
    int pair = lane >> 3, q = lane & 7;
    int nb = warp * 16 + pair;         // nodes nb, nb+4, nb+8, nb+12

    float4 acc0 = make_float4(0.f, 0.f, 0.f, 0.f);
    float4 acc1 = make_float4(0.f, 0.f, 0.f, 0.f);
    float4 acc2 = make_float4(0.f, 0.f, 0.f, 0.f);
    float4 acc3 = make_float4(0.f, 0.f, 0.f, 0.f);
    #pragma unroll 2
    for (int k4 = 0; k4 < 32; k4++) {
        float4 w0 = Ws4[(k4 * 4 + 0) * 8 + q];
        float4 w1 = Ws4[(k4 * 4 + 1) * 8 + q];
        float4 w2 = Ws4[(k4 * 4 + 2) * 8 + q];
        float4 w3 = Ws4[(k4 * 4 + 3) * 8 + q];
        float4 xv0 = xs4[(nb + 0)  * 33 + k4];
        float4 xv1 = xs4[(nb + 4)  * 33 + k4];
        float4 xv2 = xs4[(nb + 8)  * 33 + k4];
        float4 xv3 = xs4[(nb + 12) * 33 + k4];
        fma4(acc0, xv0.x, w0); fma4(acc1, xv1.x, w0);
        fma4(acc2, xv2.x, w0); fma4(acc3, xv3.x, w0);
        fma4(acc0, xv0.y, w1); fma4(acc1, xv1.y, w1);
        fma4(acc2, xv2.y, w1); fma4(acc3, xv3.y, w1);
        fma4(acc0, xv0.z, w2); fma4(acc1, xv1.z, w2);
        fma4(acc2, xv2.z, w2); fma4(acc3, xv3.z, w2);
        fma4(acc0, xv0.w, w3); fma4(acc1, xv1.w, w3);
        fma4(acc2, xv2.w, w3); fma4(acc3, xv3.w, w3);
    }

    float4 av = as4[q], dv = ad4[q];
    float4 accs[4] = {acc0, acc1, acc2, acc3};
    #pragma unroll
    for (int j = 0; j < 4; j++) {
        int node = base + nb + 4 * j;
        float4 a = accs[j];
        float ts = a.x * av.x + a.y * av.y + a.z * av.z + a.w * av.w;
        float td = a.x * dv.x + a.y * dv.y + a.z * dv.z + a.w * dv.w;
        #pragma unroll
        for (int off = 4; off >= 1; off >>= 1) {
            ts += __shfl_xor_sync(0xffffffffu, ts, off);
            td += __shfl_xor_sync(0xffffffffu, td, off);
        }
        if (node < n) {
            g_hlin1h[node * 8 + q] = pack_h4(a);
            if (q == 0) { g_as1[node] = ts; g_ad1[node] = td; }
        }
    }
}

// Fused layer-1 gather + layer-2 linear (fp16 h rows, fp32 accum).
__global__ __launch_bounds__(256) void k_gather1(
    const float* __restrict__ b1,
    const float* __restrict__ Wmu, const float* __restrict__ amus,
    const float* __restrict__ amud,
    const float* __restrict__ Wls, const float* __restrict__ alss,
    const float* __restrict__ alsd, int n)
{
    __shared__ float Wcat[32 * 32];      // [k][c]: c<16 mu, c>=16 ls
    __shared__ float4 b1s4[8];
    __shared__ float4 srcv4[8], dstv4[8];
    int tid = threadIdx.x;
    for (int i = tid; i < 1024; i += 256) {
        int k = i >> 5, c = i & 31;
        Wcat[i] = (c < 16) ? Wmu[k * 16 + c] : Wls[k * 16 + (c - 16)];
    }
    if (tid < 8) b1s4[tid] = ((const float4*)b1)[tid];
    if (tid < 32) {
        float sv = (tid < 16) ? amus[tid] : alss[tid - 16];
        float dv = (tid < 16) ? amud[tid] : alsd[tid - 16];
        ((float*)srcv4)[tid] = sv;
        ((float*)dstv4)[tid] = dv;
    }
    __syncthreads();

    int t = blockIdx.x * blockDim.x + tid;
    int node = t >> 3;
    bool act = (node < n);
    if (!act) node = n - 1;
    int lane = tid & 31;
    int q = lane & 7;
    int gbase = lane & 24;

    float ad = g_ad1[node];
    int off0 = g_off[node], off1 = g_off[node + 1];
    float4 acc = make_float4(0.f, 0.f, 0.f, 0.f);
    float s = 0.0f;
    #pragma unroll 4
    for (int i = off0; i < off1; i++) {
        int src = g_csr[i];
        float ex = __expf(lrelu(g_as1[src] + ad));
        uint2 hv = g_hlin1h[src * 8 + q];
        fma4_h(acc, ex, hv);
        s += ex;
    }
    float inv = __frcp_rn(s);
    float4 bb = b1s4[q];
    float4 h1;
    h1.x = fmaxf(fmaf(acc.x, inv, bb.x), 0.f);
    h1.y = fmaxf(fmaf(acc.y, inv, bb.y), 0.f);
    h1.z = fmaxf(fmaf(acc.z, inv, bb.z), 0.f);
    h1.w = fmaxf(fmaf(acc.w, inv, bb.w), 0.f);

    // 32x32 matmul: shuffle-broadcast h1 across the 8-lane group.
    const float4* Wc4 = (const float4*)Wcat;
    float4 o = make_float4(0.f, 0.f, 0.f, 0.f);
    #pragma unroll
    for (int r = 0; r < 8; r++) {
        float hx = __shfl_sync(0xffffffffu, h1.x, gbase + r);
        float hy = __shfl_sync(0xffffffffu, h1.y, gbase + r);
        float hz = __shfl_sync(0xffffffffu, h1.z, gbase + r);
        float hw = __shfl_sync(0xffffffffu, h1.w, gbase + r);
        fma4(o, hx, Wc4[(4 * r + 0) * 8 + q]);
        fma4(o, hy, Wc4[(4 * r + 1) * 8 + q]);
        fma4(o, hz, Wc4[(4 * r + 2) * 8 + q]);
        fma4(o, hw, Wc4[(4 * r + 3) * 8 + q]);
    }

    float4 av = srcv4[q], dv = dstv4[q];
    float ts = o.x * av.x + o.y * av.y + o.z * av.z + o.w * av.w;
    float td = o.x * dv.x + o.y * dv.y + o.z * dv.z + o.w * dv.w;
    #pragma unroll
    for (int off = 2; off >= 1; off >>= 1) {
        ts += __shfl_xor_sync(0xffffffffu, ts, off);
        td += __shfl_xor_sync(0xffffffffu, td, off);
    }
    if (act) {
        g_h23h[node * 8 + q] = pack_h4(o);
        if (q == 0) { g_src23[2 * node + 0] = ts; g_dst23[2 * node + 0] = td; }
        if (q == 4) { g_src23[2 * node + 1] = ts; g_dst23[2 * node + 1] = td; }
    }
}

// Layer-2 gather (mu+ls fused, fp16 h rows): writes final output.
__global__ __launch_bounds__(256) void k_gather23(
    const float* __restrict__ bmu, const float* __restrict__ bls,
    float* __restrict__ out, int n)
{
    int t = blockIdx.x * blockDim.x + threadIdx.x;
    int node = t >> 3;
    if (node >= n) return;
    int q = t & 7;
    float2 dv = *(const float2*)(g_dst23 + 2 * node);
    int off0 = g_off[node], off1 = g_off[node + 1];
    float4 acc = make_float4(0.f, 0.f, 0.f, 0.f);
    float smu = 0.0f, sls = 0.0f;
    bool is_mu = (q < 4);
    #pragma unroll 4
    for (int i = off0; i < off1; i++) {
        int src = g_csr[i];
        float2 sv = *(const float2*)(g_src23 + 2 * src);
        float exmu = __expf(lrelu(sv.x + dv.x));
        float exls = __expf(lrelu(sv.y + dv.y));
        smu += exmu; sls += exls;
        float ex = is_mu ? exmu : exls;
        uint2 hv = g_h23h[src * 8 + q];
        fma4_h(acc, ex, hv);
    }
    int total = n * 16;
    if (is_mu) {
        float inv = __frcp_rn(smu);
        float4 bb = ((const float4*)bmu)[q];
        float4 o;
        o.x = fmaf(acc.x, inv, bb.x); o.y = fmaf(acc.y, inv, bb.y);
        o.z = fmaf(acc.z, inv, bb.z); o.w = fmaf(acc.w, inv, bb.w);
        ((float4*)out)[node * 4 + q] = o;
    } else {
        float inv = __frcp_rn(sls);
        float4 bb = ((const float4*)bls)[q - 4];
        float4 o;
        o.x = fmaf(acc.x, inv, bb.x); o.y = fmaf(acc.y, inv, bb.y);
        o.z = fmaf(acc.z, inv, bb.z); o.w = fmaf(acc.w, inv, bb.w);
        ((float4*)(out + total))[node * 4 + (q - 4)] = o;
    }
}

// ---------------- launch (forked: gemm1 || CSR build) ----------------
extern "C" void kernel_launch(void* const* d_in, const int* in_sizes, int n_in,
                              void* d_out, int out_size)
{
    const float* x    = (const float*)d_in[0];
    const void*  ei   = d_in[1];
    const float* W1   = (const float*)d_in[2];
    const float* a1s  = (const float*)d_in[3];
    const float* a1d  = (const float*)d_in[4];
    const float* b1   = (const float*)d_in[5];
    const float* Wmu  = (const float*)d_in[6];
    const float* amus = (const float*)d_in[7];
    const float* amud = (const float*)d_in[8];
    const float* bmu  = (const float*)d_in[9];
    const float* Wls  = (const float*)d_in[10];
    const float* alss = (const float*)d_in[11];
    const float* alsd = (const float*)d_in[12];
    const float* bls  = (const float*)d_in[13];

    int n     = in_sizes[0] / 128;      // 100000
    int emain = in_sizes[1] / 2;        // 1600000
    int etot  = emain + n;
    int nblk  = (n + 1023) / 1024;      // scan blocks
    float* out = (float*)d_out;

    cudaStream_t sA = 0, sB = 0;
    cudaEvent_t evRoot = 0, evA = 0, evB = 0;
    bool forked =
        cudaStreamCreateWithFlags(&sA, cudaStreamNonBlocking) == cudaSuccess &&
        cudaStreamCreateWithFlags(&sB, cudaStreamNonBlocking) == cudaSuccess &&
        cudaEventCreateWithFlags(&evRoot, cudaEventDisableTiming) == cudaSuccess &&
        cudaEventCreateWithFlags(&evA, cudaEventDisableTiming) == cudaSuccess &&
        cudaEventCreateWithFlags(&evB, cudaEventDisableTiming) == cudaSuccess;

    if (forked && cudaEventRecord(evRoot, 0) == cudaSuccess &&
        cudaStreamWaitEvent(sA, evRoot, 0) == cudaSuccess &&
        cudaStreamWaitEvent(sB, evRoot, 0) == cudaSuccess) {
        // Chain A: dense GEMM (independent of edges)
        k_gemm1<<<(n + 63) / 64, 128, 0, sA>>>(x, W1, a1s, a1d, n);
        cudaEventRecord(evA, sA);
        // Chain B: CSR build
        k_detect<<<1, 256, 0, sB>>>((const unsigned int*)ei, emain);
        k_deginit<<<512, 256, 0, sB>>>(n);
        k_hist<<<(emain + 255) / 256, 256, 0, sB>>>(ei, emain);
        k_scanA<<<nblk, 256, 0, sB>>>(n);
        k_scanB<<<1, 128, 0, sB>>>(nblk);
        k_scanC<<<nblk, 256, 0, sB>>>(n, etot);
        k_scatter<<<(etot + 255) / 256, 256, 0, sB>>>(ei, emain, n);
        cudaEventRecord(evB, sB);
        // Join back onto the capture-origin stream
        cudaStreamWaitEvent(0, evA, 0);
        cudaStreamWaitEvent(0, evB, 0);
        k_gather1<<<(n * 8 + 255) / 256, 256>>>(b1, Wmu, amus, amud,
                                                Wls, alss, alsd, n);
        k_gather23<<<(n * 8 + 255) / 256, 256>>>(bmu, bls, out, n);
    } else {
        // Fallback: serial on the origin stream
        k_detect<<<1, 256>>>((const unsigned int*)ei, emain);
        k_deginit<<<512, 256>>>(n);
        k_hist<<<(emain + 255) / 256, 256>>>(ei, emain);
        k_gemm1<<<(n + 63) / 64, 128>>>(x, W1, a1s, a1d, n);
        k_scanA<<<nblk, 256>>>(n);
        k_scanB<<<1, 128>>>(nblk);
        k_scanC<<<nblk, 256>>>(n, etot);
        k_scatter<<<(etot + 255) / 256, 256>>>(ei, emain, n);
        k_gather1<<<(n * 8 + 255) / 256, 256>>>(b1, Wmu, amus, amud,
                                                Wls, alss, alsd, n);
        k_gather23<<<(n * 8 + 255) / 256, 256>>>(bmu, bls, out, n);
    }

    if (evRoot) cudaEventDestroy(evRoot);
    if (evA)    cudaEventDestroy(evA);
    if (evB)    cudaEventDestroy(evB);
    if (sA)     cudaStreamDestroy(sA);
    if (sB)     cudaStreamDestroy(sB);
}